// round 4
// baseline (speedup 1.0000x reference)
#include <cuda_runtime.h>
#include <cuda_bf16.h>
#include <math.h>
#include <stdint.h>

// Problem constants (B=2,S=2048,H=1024,E=64,K=8,F=512,cap=2.0)
#define TOK   4096
#define HD    1024
#define NE    64
#define KSEL  8
#define FF    512
#define NA    (TOK*KSEL)
#define CAP   1024

// ---------------- scratch (__device__ globals) ----------------
__device__ __align__(16) float g_logits[(size_t)TOK * NE];
__device__ int   g_sel[NA];
__device__ float g_wgt[NA];
__device__ int   g_rowtok[NE * CAP];
__device__ float g_wslot[NE * CAP];
__device__ int   g_cnt[NE];
__device__ __align__(16) float g_act[(size_t)NE * CAP * FF];   // 134MB, tf32-rounded fp32

// ---------------- helpers ----------------
__device__ __forceinline__ uint32_t smem_u32(const void* p) {
    uint32_t a;
    asm("{ .reg .u64 t; cvta.to.shared.u64 t, %1; cvt.u32.u64 %0, t; }" : "=r"(a) : "l"(p));
    return a;
}
__device__ __forceinline__ void ldsm4(uint32_t* r, uint32_t addr) {
    asm volatile("ldmatrix.sync.aligned.m8n8.x4.shared.b16 {%0,%1,%2,%3}, [%4];"
                 : "=r"(r[0]), "=r"(r[1]), "=r"(r[2]), "=r"(r[3]) : "r"(addr));
}
__device__ __forceinline__ void mma_tf32(float* c, const uint32_t* a, uint32_t b0, uint32_t b1) {
    asm volatile("mma.sync.aligned.m16n8k8.row.col.f32.tf32.tf32.f32 "
                 "{%0,%1,%2,%3}, {%4,%5,%6,%7}, {%8,%9}, {%0,%1,%2,%3};"
                 : "+f"(c[0]), "+f"(c[1]), "+f"(c[2]), "+f"(c[3])
                 : "r"(a[0]), "r"(a[1]), "r"(a[2]), "r"(a[3]), "r"(b0), "r"(b1));
}
// round-to-nearest tf32 (zero-mean error; raw fp32 into tf32 MMA would truncate -> bias)
__device__ __forceinline__ float rna(float x) {
    uint32_t r;
    asm("cvt.rna.tf32.f32 %0, %1;" : "=r"(r) : "f"(x));
    return __uint_as_float(r);
}
__device__ __forceinline__ float4 rna4(float4 v) {
    return make_float4(rna(v.x), rna(v.y), rna(v.z), rna(v.w));
}

#define STR 36            // fp32 smem stride: rows 144B (16B-aligned for ldmatrix), conflict-free
#define STRB (STR * 4)    // bytes

// ---------------- 1) router logits ----------------
#define RT 8
__global__ __launch_bounds__(256) void router_kernel(const float* __restrict__ x,
                                                     const float* __restrict__ wg) {
    __shared__ __align__(16) float xs[RT][HD];
    int t0 = blockIdx.x * RT;
    for (int i = threadIdx.x; i < RT * HD / 4; i += 256) {
        int r = i >> 8;
        int c = (i & 255) << 2;
        *(float4*)&xs[r][c] = *(const float4*)&x[(size_t)(t0 + r) * HD + c];
    }
    __syncthreads();
    int e  = threadIdx.x & 63;
    int tg = threadIdx.x >> 6;
    float acc0 = 0.f, acc1 = 0.f;
#pragma unroll 4
    for (int j = 0; j < HD; ++j) {
        float w = wg[(size_t)j * NE + e];
        acc0 += w * xs[tg * 2 + 0][j];
        acc1 += w * xs[tg * 2 + 1][j];
    }
    g_logits[(size_t)(t0 + tg * 2 + 0) * NE + e] = acc0;
    g_logits[(size_t)(t0 + tg * 2 + 1) * NE + e] = acc1;
}

// ---------------- 2) softmax + top-8 + renorm ----------------
__global__ void topk_kernel() {
    int t = blockIdx.x * blockDim.x + threadIdx.x;
    if (t >= TOK) return;
    const float* l = g_logits + (size_t)t * NE;
    float m = -INFINITY;
    for (int e = 0; e < NE; ++e) m = fmaxf(m, l[e]);
    float s = 0.f;
    for (int e = 0; e < NE; ++e) s += expf(l[e] - m);
    unsigned long long mask = 0ull;
    float wv[KSEL]; int se[KSEL];
    float wsum = 0.f;
    for (int k = 0; k < KSEL; ++k) {
        float best = -INFINITY; int be = 0;
        for (int e = 0; e < NE; ++e) {
            if ((mask >> e) & 1ull) continue;
            float v = l[e];
            if (v > best) { best = v; be = e; }
        }
        mask |= (1ull << be);
        float p = expf(best - m) / s;
        wv[k] = p; se[k] = be; wsum += p;
    }
    float inv = 1.f / wsum;
    for (int k = 0; k < KSEL; ++k) {
        g_sel[t * KSEL + k] = se[k];
        g_wgt[t * KSEL + k] = wv[k] * inv;
    }
}

// ---------------- 3) dispatch: stable per-expert ranks ----------------
__global__ __launch_bounds__(256) void dispatch_kernel() {
    int e = blockIdx.x;
    __shared__ int stot[8];
    int tid = threadIdx.x, wid = tid >> 5, lane = tid & 31;
    int run = 0;
    for (int base = 0; base < NA; base += 256) {
        int a = base + tid;
        int m = (g_sel[a] == e) ? 1 : 0;
        unsigned b = __ballot_sync(0xffffffffu, m);
        int wpref = __popc(b & ((1u << lane) - 1u));
        if (lane == 0) stot[wid] = __popc(b);
        __syncthreads();
        int before = 0, total = 0;
#pragma unroll
        for (int w = 0; w < 8; ++w) {
            int c = stot[w];
            if (w < wid) before += c;
            total += c;
        }
        if (m) {
            int p = run + before + wpref;
            if (p < CAP) {
                g_rowtok[e * CAP + p] = a / KSEL;
                g_wslot[e * CAP + p]  = g_wgt[a];
            }
        }
        run += total;
        __syncthreads();
    }
    if (tid == 0) g_cnt[e] = (run < CAP) ? run : CAP;
}

// ---------------- 4) zero output ----------------
__global__ void zero_out_kernel(float4* o) {
    int i = blockIdx.x * blockDim.x + threadIdx.x;
    o[i] = make_float4(0.f, 0.f, 0.f, 0.f);
}

// ---------------- 5) GEMM-A: act = silu(x@w1)*(x@w3)  [mma.sync tf32] ----------------
// block tile 128m x 64n x 32k; 8 warps = 4m x 2n; warp tile 32x32
__global__ __launch_bounds__(256, 1) void gemm_a_mma(const float* __restrict__ x,
                                                     const float* __restrict__ w1,
                                                     const float* __restrict__ w3) {
    __shared__ __align__(16) float Asm[128 * STR];
    __shared__ __align__(16) float B1sm[64 * STR];
    __shared__ __align__(16) float B3sm[64 * STR];

    const int e = blockIdx.z;
    const int cnt = g_cnt[e];
    const int m_base = blockIdx.y * 128;
    if (m_base >= cnt) return;
    const int n_base = blockIdx.x * 64;

    const int tid = threadIdx.x, lane = tid & 31, wid = tid >> 5;
    const int wm = wid & 3, wn = wid >> 2;

    // A load mapping: 128 rows x 32 k; thread: row=tid>>1, half=tid&1 (16 floats)
    const int arow = tid >> 1, ahalf = tid & 1;
    int gr = m_base + arow; if (gr >= cnt) gr = cnt - 1;
    const float* xr = x + (size_t)g_rowtok[e * CAP + gr] * HD + ahalf * 16;
    // B load mapping: n4 = (tid&15)*4, k = (tid>>4) + 16*kk  (store-transposed, conflict-free)
    const int bn4 = (tid & 15) * 4, bku = tid >> 4;

    const uint32_t sA = smem_u32(Asm), sB1 = smem_u32(B1sm), sB3 = smem_u32(B3sm);
    // ldmatrix lane offsets
    const uint32_t aoff = (uint32_t)(wm * 32 + (lane & 15)) * STRB + (uint32_t)(lane >> 4) * 16;
    const uint32_t boff = (uint32_t)(wn * 32 + (lane & 15)) * STRB + (uint32_t)(lane >> 4) * 16;

    float acc1[2][4][4] = {}, acc3[2][4][4] = {};
    float4 pa[4], p1[2], p3[2];

    // prefetch chunk 0
    {
        const float* w1p = w1 + ((size_t)e * HD + bku) * FF + n_base + bn4;
        const float* w3p = w3 + ((size_t)e * HD + bku) * FF + n_base + bn4;
#pragma unroll
        for (int j = 0; j < 4; ++j) pa[j] = *(const float4*)(xr + j * 4);
#pragma unroll
        for (int kk = 0; kk < 2; ++kk) {
            p1[kk] = *(const float4*)(w1p + (size_t)16 * kk * FF);
            p3[kk] = *(const float4*)(w3p + (size_t)16 * kk * FF);
        }
    }

    for (int c = 0; c < HD / 32; ++c) {
        __syncthreads();
        // store to smem (with tf32 rounding)
        {
            float* ap = &Asm[arow * STR + ahalf * 16];
#pragma unroll
            for (int j = 0; j < 4; ++j) *(float4*)(ap + j * 4) = rna4(pa[j]);
#pragma unroll
            for (int kk = 0; kk < 2; ++kk) {
                const float* f1 = (const float*)&p1[kk];
                const float* f3 = (const float*)&p3[kk];
#pragma unroll
                for (int j = 0; j < 4; ++j) {
                    B1sm[(bn4 + j) * STR + bku + 16 * kk] = rna(f1[j]);
                    B3sm[(bn4 + j) * STR + bku + 16 * kk] = rna(f3[j]);
                }
            }
        }
        __syncthreads();
        // prefetch next chunk
        if (c + 1 < HD / 32) {
            int k0 = (c + 1) * 32;
            const float* w1p = w1 + ((size_t)e * HD + k0 + bku) * FF + n_base + bn4;
            const float* w3p = w3 + ((size_t)e * HD + k0 + bku) * FF + n_base + bn4;
#pragma unroll
            for (int j = 0; j < 4; ++j) pa[j] = *(const float4*)(xr + k0 + j * 4);
#pragma unroll
            for (int kk = 0; kk < 2; ++kk) {
                p1[kk] = *(const float4*)(w1p + (size_t)16 * kk * FF);
                p3[kk] = *(const float4*)(w3p + (size_t)16 * kk * FF);
            }
        }
        // compute: 4 k8 steps
#pragma unroll
        for (int ks = 0; ks < 4; ++ks) {
            uint32_t a[2][4], b1r[2][4], b3r[2][4];
#pragma unroll
            for (int mf = 0; mf < 2; ++mf)
                ldsm4(a[mf], sA + aoff + (uint32_t)mf * 16 * STRB + (uint32_t)ks * 32);
#pragma unroll
            for (int g = 0; g < 2; ++g) {
                uint32_t o = boff + (uint32_t)g * 16 * STRB + (uint32_t)ks * 32;
                ldsm4(b1r[g], sB1 + o);
                ldsm4(b3r[g], sB3 + o);
            }
#pragma unroll
            for (int nf = 0; nf < 4; ++nf) {
                int g = nf >> 1, sub = nf & 1;
#pragma unroll
                for (int mf = 0; mf < 2; ++mf) {
                    mma_tf32(acc1[mf][nf], a[mf], b1r[g][sub], b1r[g][2 + sub]);
                    mma_tf32(acc3[mf][nf], a[mf], b3r[g][sub], b3r[g][2 + sub]);
                }
            }
        }
    }

    // epilogue: silu(g)*u -> tf32-rounded fp32 to g_act
#pragma unroll
    for (int mf = 0; mf < 2; ++mf) {
#pragma unroll
        for (int half = 0; half < 2; ++half) {
            int r = wm * 32 + mf * 16 + (lane >> 2) + half * 8;
            int grr = m_base + r;
            if (grr < cnt) {
                size_t rb = ((size_t)e * CAP + grr) * FF + n_base + wn * 32 + (lane & 3) * 2;
#pragma unroll
                for (int nf = 0; nf < 4; ++nf) {
                    float g0 = acc1[mf][nf][half * 2],     u0 = acc3[mf][nf][half * 2];
                    float g1 = acc1[mf][nf][half * 2 + 1], u1 = acc3[mf][nf][half * 2 + 1];
                    float a0 = (g0 / (1.f + expf(-g0))) * u0;
                    float a1 = (g1 / (1.f + expf(-g1))) * u1;
                    *(float2*)&g_act[rb + nf * 8] = make_float2(rna(a0), rna(a1));
                }
            }
        }
    }
}

// ---------------- 6) GEMM-B: out += w * (act @ w2)  [mma.sync tf32 + scatter] ----------------
__global__ __launch_bounds__(256, 1) void gemm_b_mma(const float* __restrict__ w2,
                                                     float* __restrict__ out) {
    __shared__ __align__(16) float Asm[128 * STR];
    __shared__ __align__(16) float Bsm[64 * STR];

    const int e = blockIdx.z;
    const int cnt = g_cnt[e];
    const int m_base = blockIdx.y * 128;
    if (m_base >= cnt) return;
    const int n_base = blockIdx.x * 64;

    const int tid = threadIdx.x, lane = tid & 31, wid = tid >> 5;
    const int wm = wid & 3, wn = wid >> 2;

    const int arow = tid >> 1, ahalf = tid & 1;
    int gr = m_base + arow; if (gr >= cnt) gr = cnt - 1;
    const float* actr = g_act + ((size_t)e * CAP + gr) * FF + ahalf * 16;
    const int bn4 = (tid & 15) * 4, bku = tid >> 4;

    const uint32_t sA = smem_u32(Asm), sB = smem_u32(Bsm);
    const uint32_t aoff = (uint32_t)(wm * 32 + (lane & 15)) * STRB + (uint32_t)(lane >> 4) * 16;
    const uint32_t boff = (uint32_t)(wn * 32 + (lane & 15)) * STRB + (uint32_t)(lane >> 4) * 16;

    float acc[2][4][4] = {};
    float4 pa[4], pb[2];

    {
        const float* w2p = w2 + ((size_t)e * FF + bku) * HD + n_base + bn4;
#pragma unroll
        for (int j = 0; j < 4; ++j) pa[j] = *(const float4*)(actr + j * 4);
#pragma unroll
        for (int kk = 0; kk < 2; ++kk) pb[kk] = *(const float4*)(w2p + (size_t)16 * kk * HD);
    }

    for (int c = 0; c < FF / 32; ++c) {
        __syncthreads();
        {
            float* ap = &Asm[arow * STR + ahalf * 16];
#pragma unroll
            for (int j = 0; j < 4; ++j) *(float4*)(ap + j * 4) = pa[j];  // act already tf32-rounded
#pragma unroll
            for (int kk = 0; kk < 2; ++kk) {
                const float* f = (const float*)&pb[kk];
#pragma unroll
                for (int j = 0; j < 4; ++j)
                    Bsm[(bn4 + j) * STR + bku + 16 * kk] = rna(f[j]);
            }
        }
        __syncthreads();
        if (c + 1 < FF / 32) {
            int k0 = (c + 1) * 32;
            const float* w2p = w2 + ((size_t)e * FF + k0 + bku) * HD + n_base + bn4;
#pragma unroll
            for (int j = 0; j < 4; ++j) pa[j] = *(const float4*)(actr + k0 + j * 4);
#pragma unroll
            for (int kk = 0; kk < 2; ++kk) pb[kk] = *(const float4*)(w2p + (size_t)16 * kk * HD);
        }
#pragma unroll
        for (int ks = 0; ks < 4; ++ks) {
            uint32_t a[2][4], br[2][4];
#pragma unroll
            for (int mf = 0; mf < 2; ++mf)
                ldsm4(a[mf], sA + aoff + (uint32_t)mf * 16 * STRB + (uint32_t)ks * 32);
#pragma unroll
            for (int g = 0; g < 2; ++g)
                ldsm4(br[g], sB + boff + (uint32_t)g * 16 * STRB + (uint32_t)ks * 32);
#pragma unroll
            for (int nf = 0; nf < 4; ++nf) {
                int g = nf >> 1, sub = nf & 1;
#pragma unroll
                for (int mf = 0; mf < 2; ++mf)
                    mma_tf32(acc[mf][nf], a[mf], br[g][sub], br[g][2 + sub]);
            }
        }
    }

    // epilogue: weighted atomic scatter to out
#pragma unroll
    for (int mf = 0; mf < 2; ++mf) {
#pragma unroll
        for (int half = 0; half < 2; ++half) {
            int r = wm * 32 + mf * 16 + (lane >> 2) + half * 8;
            int grr = m_base + r;
            if (grr < cnt) {
                int tok = g_rowtok[e * CAP + grr];
                float w  = g_wslot[e * CAP + grr];
                float* op = out + (size_t)tok * HD + n_base + wn * 32 + (lane & 3) * 2;
#pragma unroll
                for (int nf = 0; nf < 4; ++nf) {
                    atomicAdd(op + nf * 8,     w * acc[mf][nf][half * 2]);
                    atomicAdd(op + nf * 8 + 1, w * acc[mf][nf][half * 2 + 1]);
                }
            }
        }
    }
}

// ---------------- 7) copy router logits into output tail ----------------
__global__ void copy_logits_kernel(float* __restrict__ dst) {
    int i = blockIdx.x * blockDim.x + threadIdx.x;
    int n = TOK * NE;
    for (; i < n; i += gridDim.x * blockDim.x) dst[i] = g_logits[i];
}

// ---------------- host launcher ----------------
extern "C" void kernel_launch(void* const* d_in, const int* in_sizes, int n_in,
                              void* d_out, int out_size) {
    const float* x  = (const float*)d_in[0];
    const float* wg = (const float*)d_in[1];
    const float* w1 = (const float*)d_in[2];
    const float* w3 = (const float*)d_in[3];
    const float* w2 = (const float*)d_in[4];
    float* out = (float*)d_out;

    // zero_out first so ncu -s 5 lands on gemm_b
    zero_out_kernel<<<TOK * HD / 4 / 256, 256>>>((float4*)out);
    router_kernel<<<TOK / RT, 256>>>(x, wg);
    topk_kernel<<<(TOK + 255) / 256, 256>>>();
    dispatch_kernel<<<NE, 256>>>();

    dim3 ga(FF / 64, CAP / 128, NE);      // (8, 8, 64)
    gemm_a_mma<<<ga, 256>>>(x, w1, w3);
    dim3 gb(HD / 64, CAP / 128, NE);      // (16, 8, 64)
    gemm_b_mma<<<gb, 256>>>(w2, out);

    if ((size_t)out_size >= (size_t)TOK * HD + (size_t)TOK * NE) {
        copy_logits_kernel<<<256, 256>>>(out + (size_t)TOK * HD);
    }
}

// round 5
// speedup vs baseline: 1.1672x; 1.1672x over previous
#include <cuda_runtime.h>
#include <cuda_bf16.h>
#include <math.h>
#include <stdint.h>

// Problem constants (B=2,S=2048,H=1024,E=64,K=8,F=512,cap=2.0)
#define TOK   4096
#define HD    1024
#define NE    64
#define KSEL  8
#define FF    512
#define NA    (TOK*KSEL)
#define CAP   1024

// ---------------- scratch (__device__ globals) ----------------
__device__ __align__(16) float g_logits[(size_t)TOK * NE];
__device__ int   g_sel[NA];
__device__ float g_wgt[NA];
__device__ int   g_rowtok[NE * CAP];
__device__ float g_wslot[NE * CAP];
__device__ int   g_cnt[NE];
__device__ __align__(16) __nv_bfloat16 g_act_hi[(size_t)NE * CAP * FF];  // 64MB
__device__ __align__(16) __nv_bfloat16 g_act_lo[(size_t)NE * CAP * FF];  // 64MB

// ---------------- helpers ----------------
__device__ __forceinline__ uint32_t smem_u32(const void* p) {
    uint32_t a;
    asm("{ .reg .u64 t; cvta.to.shared.u64 t, %1; cvt.u32.u64 %0, t; }" : "=r"(a) : "l"(p));
    return a;
}
__device__ __forceinline__ void ldsm4(uint32_t* r, uint32_t addr) {
    asm volatile("ldmatrix.sync.aligned.m8n8.x4.shared.b16 {%0,%1,%2,%3}, [%4];"
                 : "=r"(r[0]), "=r"(r[1]), "=r"(r[2]), "=r"(r[3]) : "r"(addr));
}
__device__ __forceinline__ void ldsm4t(uint32_t* r, uint32_t addr) {
    asm volatile("ldmatrix.sync.aligned.m8n8.x4.trans.shared.b16 {%0,%1,%2,%3}, [%4];"
                 : "=r"(r[0]), "=r"(r[1]), "=r"(r[2]), "=r"(r[3]) : "r"(addr));
}
__device__ __forceinline__ void mma16816(float* c, const uint32_t* a, const uint32_t* b) {
    asm volatile("mma.sync.aligned.m16n8k16.row.col.f32.bf16.bf16.f32 "
                 "{%0,%1,%2,%3}, {%4,%5,%6,%7}, {%8,%9}, {%0,%1,%2,%3};"
                 : "+f"(c[0]), "+f"(c[1]), "+f"(c[2]), "+f"(c[3])
                 : "r"(a[0]), "r"(a[1]), "r"(a[2]), "r"(a[3]), "r"(b[0]), "r"(b[1]));
}
// split two floats into bf16x2 hi + bf16x2 lo (residual)
__device__ __forceinline__ void split2(float a, float b, uint32_t& h, uint32_t& l) {
    __nv_bfloat162 ph = __floats2bfloat162_rn(a, b);
    float ra = a - __bfloat162float(ph.x);
    float rb = b - __bfloat162float(ph.y);
    __nv_bfloat162 pl = __floats2bfloat162_rn(ra, rb);
    h = *(uint32_t*)&ph;
    l = *(uint32_t*)&pl;
}

// smem strides (bf16 elements)
#define ASTR 40   // rows 80B = 20 words: banks 20r%32 distinct over 8 rows
#define BSTR 72   // rows 144B = 36 words: banks 4r%32 distinct over 8 rows

// ---------------- 1) router logits (+ zero g_cnt for dispatch) ----------------
#define RT 8
__global__ __launch_bounds__(256) void router_kernel(const float* __restrict__ x,
                                                     const float* __restrict__ wg) {
    if (blockIdx.x == 0 && threadIdx.x < NE) g_cnt[threadIdx.x] = 0;
    __shared__ __align__(16) float xs[RT][HD];
    int t0 = blockIdx.x * RT;
    for (int i = threadIdx.x; i < RT * HD / 4; i += 256) {
        int r = i >> 8;
        int c = (i & 255) << 2;
        *(float4*)&xs[r][c] = *(const float4*)&x[(size_t)(t0 + r) * HD + c];
    }
    __syncthreads();
    int e  = threadIdx.x & 63;
    int tg = threadIdx.x >> 6;
    float acc0 = 0.f, acc1 = 0.f;
#pragma unroll 4
    for (int j = 0; j < HD; ++j) {
        float w = wg[(size_t)j * NE + e];
        acc0 += w * xs[tg * 2 + 0][j];
        acc1 += w * xs[tg * 2 + 1][j];
    }
    g_logits[(size_t)(t0 + tg * 2 + 0) * NE + e] = acc0;
    g_logits[(size_t)(t0 + tg * 2 + 1) * NE + e] = acc1;
}

// ---------------- 2) softmax + top-8 + renorm ----------------
__global__ void topk_kernel() {
    int t = blockIdx.x * blockDim.x + threadIdx.x;
    if (t >= TOK) return;
    const float* l = g_logits + (size_t)t * NE;
    float m = -INFINITY;
    for (int e = 0; e < NE; ++e) m = fmaxf(m, l[e]);
    float s = 0.f;
    for (int e = 0; e < NE; ++e) s += expf(l[e] - m);
    unsigned long long mask = 0ull;
    float wv[KSEL]; int se[KSEL];
    float wsum = 0.f;
    for (int k = 0; k < KSEL; ++k) {
        float best = -INFINITY; int be = 0;
        for (int e = 0; e < NE; ++e) {
            if ((mask >> e) & 1ull) continue;
            float v = l[e];
            if (v > best) { best = v; be = e; }
        }
        mask |= (1ull << be);
        float p = expf(best - m) / s;
        wv[k] = p; se[k] = be; wsum += p;
    }
    float inv = 1.f / wsum;
    for (int k = 0; k < KSEL; ++k) {
        g_sel[t * KSEL + k] = se[k];
        g_wgt[t * KSEL + k] = wv[k] * inv;
    }
}

// ---------------- 3) dispatch: atomic rank (order-free; no drops possible at CAP=2x) ----------------
__global__ __launch_bounds__(256) void dispatch_kernel() {
    int a = blockIdx.x * blockDim.x + threadIdx.x;
    if (a >= NA) return;
    int e = g_sel[a];
    int p = atomicAdd(&g_cnt[e], 1);
    if (p < CAP) {
        g_rowtok[e * CAP + p] = a >> 3;     // a / KSEL
        g_wslot[e * CAP + p]  = g_wgt[a];
    }
}

// ---------------- 4) zero output ----------------
__global__ void zero_out_kernel(float4* o) {
    int i = blockIdx.x * blockDim.x + threadIdx.x;
    o[i] = make_float4(0.f, 0.f, 0.f, 0.f);
}

// ---------------- 5) GEMM-A: act = silu(x@w1)*(x@w3)  [mma.sync bf16 x3] ----------------
__global__ __launch_bounds__(256, 1) void gemm_a_mma(const float* __restrict__ x,
                                                     const float* __restrict__ w1,
                                                     const float* __restrict__ w3) {
    __shared__ __align__(16) __nv_bfloat16 Ah[128 * ASTR], Al[128 * ASTR];
    __shared__ __align__(16) __nv_bfloat16 B1h[32 * BSTR], B1l[32 * BSTR];
    __shared__ __align__(16) __nv_bfloat16 B3h[32 * BSTR], B3l[32 * BSTR];

    const int e = blockIdx.z;
    int cnt = g_cnt[e]; if (cnt > CAP) cnt = CAP;
    const int m_base = blockIdx.y * 128;
    if (m_base >= cnt) return;
    const int n_base = blockIdx.x * 64;

    const int tid = threadIdx.x, lane = tid & 31, wid = tid >> 5;
    const int wm = wid & 3, wn = wid >> 2;

    const int arow = tid >> 1, ahalf = tid & 1;          // A: 128 rows x 32 k
    int gr = m_base + arow; if (gr >= cnt) gr = cnt - 1;
    const float* xr = x + (size_t)g_rowtok[e * CAP + gr] * HD;
    const int bk = tid >> 3, bn0 = (tid & 7) * 8;        // B: 32 k x 64 n

    const uint32_t sAh = smem_u32(Ah), sAl = smem_u32(Al);
    const uint32_t s1h = smem_u32(B1h), s1l = smem_u32(B1l);
    const uint32_t s3h = smem_u32(B3h), s3l = smem_u32(B3l);

    const uint32_t aoff = (uint32_t)(wm * 32 + (lane & 15)) * (ASTR * 2) + (uint32_t)(lane >> 4) * 16;
    const uint32_t boff = (uint32_t)(lane & 15) * (BSTR * 2) + (uint32_t)(lane >> 4) * 16 + (uint32_t)wn * 64;

    float acc1[2][4][4] = {}, acc3[2][4][4] = {};
    float4 pa[4], p1[2], p3[2];

    // prefetch chunk 0
    {
        const float* w1p = w1 + ((size_t)e * HD + bk) * FF + n_base + bn0;
        const float* w3p = w3 + ((size_t)e * HD + bk) * FF + n_base + bn0;
#pragma unroll
        for (int j = 0; j < 4; ++j) pa[j] = *(const float4*)(xr + ahalf * 16 + j * 4);
#pragma unroll
        for (int q = 0; q < 2; ++q) { p1[q] = *(const float4*)(w1p + q * 4); p3[q] = *(const float4*)(w3p + q * 4); }
    }

    for (int c = 0; c < HD / 32; ++c) {
        __syncthreads();
        // store prefetched regs -> smem (hi/lo split)
        {
            uint32_t ab = (uint32_t)arow * (ASTR * 2) + (uint32_t)ahalf * 32;
#pragma unroll
            for (int j = 0; j < 4; ++j) {
                uint32_t h0, l0, h1, l1;
                split2(pa[j].x, pa[j].y, h0, l0);
                split2(pa[j].z, pa[j].w, h1, l1);
                *(uint2*)((char*)Ah + ab + j * 8) = make_uint2(h0, h1);
                *(uint2*)((char*)Al + ab + j * 8) = make_uint2(l0, l1);
            }
            uint32_t bb = (uint32_t)bk * (BSTR * 2) + (uint32_t)bn0 * 2;
            float f1[8] = {p1[0].x, p1[0].y, p1[0].z, p1[0].w, p1[1].x, p1[1].y, p1[1].z, p1[1].w};
            float f3[8] = {p3[0].x, p3[0].y, p3[0].z, p3[0].w, p3[1].x, p3[1].y, p3[1].z, p3[1].w};
            uint32_t h[4], l[4];
#pragma unroll
            for (int q = 0; q < 4; ++q) split2(f1[q * 2], f1[q * 2 + 1], h[q], l[q]);
            *(uint4*)((char*)B1h + bb) = make_uint4(h[0], h[1], h[2], h[3]);
            *(uint4*)((char*)B1l + bb) = make_uint4(l[0], l[1], l[2], l[3]);
#pragma unroll
            for (int q = 0; q < 4; ++q) split2(f3[q * 2], f3[q * 2 + 1], h[q], l[q]);
            *(uint4*)((char*)B3h + bb) = make_uint4(h[0], h[1], h[2], h[3]);
            *(uint4*)((char*)B3l + bb) = make_uint4(l[0], l[1], l[2], l[3]);
        }
        __syncthreads();
        // prefetch next chunk
        if (c + 1 < HD / 32) {
            int k0 = (c + 1) * 32;
            const float* w1p = w1 + ((size_t)e * HD + k0 + bk) * FF + n_base + bn0;
            const float* w3p = w3 + ((size_t)e * HD + k0 + bk) * FF + n_base + bn0;
#pragma unroll
            for (int j = 0; j < 4; ++j) pa[j] = *(const float4*)(xr + k0 + ahalf * 16 + j * 4);
#pragma unroll
            for (int q = 0; q < 2; ++q) { p1[q] = *(const float4*)(w1p + q * 4); p3[q] = *(const float4*)(w3p + q * 4); }
        }
        // compute: 2 k16 steps
#pragma unroll
        for (int ks = 0; ks < 2; ++ks) {
            uint32_t ah[2][4], al[2][4];
#pragma unroll
            for (int mf = 0; mf < 2; ++mf) {
                uint32_t ao = aoff + (uint32_t)mf * 16 * (ASTR * 2) + (uint32_t)ks * 32;
                ldsm4(ah[mf], sAh + ao);
                ldsm4(al[mf], sAl + ao);
            }
#pragma unroll
            for (int pr = 0; pr < 2; ++pr) {
                uint32_t o = boff + (uint32_t)ks * 16 * (BSTR * 2) + (uint32_t)pr * 32;
                uint32_t b1h[4], b1l[4], b3h[4], b3l[4];
                ldsm4t(b1h, s1h + o); ldsm4t(b1l, s1l + o);
                ldsm4t(b3h, s3h + o); ldsm4t(b3l, s3l + o);
#pragma unroll
                for (int sub = 0; sub < 2; ++sub) {
                    int nf = pr * 2 + sub;
#pragma unroll
                    for (int mf = 0; mf < 2; ++mf) {
                        mma16816(acc1[mf][nf], ah[mf], b1h + sub * 2);
                        mma16816(acc1[mf][nf], ah[mf], b1l + sub * 2);
                        mma16816(acc1[mf][nf], al[mf], b1h + sub * 2);
                        mma16816(acc3[mf][nf], ah[mf], b3h + sub * 2);
                        mma16816(acc3[mf][nf], ah[mf], b3l + sub * 2);
                        mma16816(acc3[mf][nf], al[mf], b3h + sub * 2);
                    }
                }
            }
        }
    }

    // epilogue: silu(g)*u -> bf16 hi/lo to g_act
#pragma unroll
    for (int mf = 0; mf < 2; ++mf) {
#pragma unroll
        for (int half = 0; half < 2; ++half) {
            int r = wm * 32 + mf * 16 + (lane >> 2) + half * 8;
            int grr = m_base + r;
            if (grr < cnt) {
                size_t rb = ((size_t)e * CAP + grr) * FF + n_base + wn * 32 + (lane & 3) * 2;
#pragma unroll
                for (int nf = 0; nf < 4; ++nf) {
                    float g0 = acc1[mf][nf][half * 2],     u0 = acc3[mf][nf][half * 2];
                    float g1 = acc1[mf][nf][half * 2 + 1], u1 = acc3[mf][nf][half * 2 + 1];
                    float a0 = (g0 / (1.f + expf(-g0))) * u0;
                    float a1 = (g1 / (1.f + expf(-g1))) * u1;
                    uint32_t hh, ll;
                    split2(a0, a1, hh, ll);
                    *(uint32_t*)&g_act_hi[rb + nf * 8] = hh;
                    *(uint32_t*)&g_act_lo[rb + nf * 8] = ll;
                }
            }
        }
    }
}

// ---------------- 6) GEMM-B: out += w * (act @ w2)  [mma.sync bf16 x3 + scatter] ----------------
__global__ __launch_bounds__(256, 1) void gemm_b_mma(const float* __restrict__ w2,
                                                     float* __restrict__ out) {
    __shared__ __align__(16) __nv_bfloat16 Ah[128 * ASTR], Al[128 * ASTR];
    __shared__ __align__(16) __nv_bfloat16 Bh[32 * BSTR], Bl[32 * BSTR];

    const int e = blockIdx.z;
    int cnt = g_cnt[e]; if (cnt > CAP) cnt = CAP;
    const int m_base = blockIdx.y * 128;
    if (m_base >= cnt) return;
    const int n_base = blockIdx.x * 64;

    const int tid = threadIdx.x, lane = tid & 31, wid = tid >> 5;
    const int wm = wid & 3, wn = wid >> 2;

    const int arow = tid >> 1, ahalf = tid & 1;
    int gr = m_base + arow; if (gr >= cnt) gr = cnt - 1;
    const __nv_bfloat16* ahp = g_act_hi + ((size_t)e * CAP + gr) * FF;
    const __nv_bfloat16* alp = g_act_lo + ((size_t)e * CAP + gr) * FF;
    const int bk = tid >> 3, bn0 = (tid & 7) * 8;

    const uint32_t sAh = smem_u32(Ah), sAl = smem_u32(Al);
    const uint32_t sBh = smem_u32(Bh), sBl = smem_u32(Bl);
    const uint32_t aoff = (uint32_t)(wm * 32 + (lane & 15)) * (ASTR * 2) + (uint32_t)(lane >> 4) * 16;
    const uint32_t boff = (uint32_t)(lane & 15) * (BSTR * 2) + (uint32_t)(lane >> 4) * 16 + (uint32_t)wn * 64;

    float acc[2][4][4] = {};
    uint4 qh[2], ql[2];
    float4 pb[2];

    {
        const float* w2p = w2 + ((size_t)e * FF + bk) * HD + n_base + bn0;
#pragma unroll
        for (int q = 0; q < 2; ++q) {
            qh[q] = *(const uint4*)(ahp + ahalf * 16 + q * 8);
            ql[q] = *(const uint4*)(alp + ahalf * 16 + q * 8);
            pb[q] = *(const float4*)(w2p + q * 4);
        }
    }

    for (int c = 0; c < FF / 32; ++c) {
        __syncthreads();
        {
            uint32_t ab = (uint32_t)arow * (ASTR * 2) + (uint32_t)ahalf * 32;
#pragma unroll
            for (int q = 0; q < 2; ++q) {
                *(uint4*)((char*)Ah + ab + q * 16) = qh[q];
                *(uint4*)((char*)Al + ab + q * 16) = ql[q];
            }
            uint32_t bb = (uint32_t)bk * (BSTR * 2) + (uint32_t)bn0 * 2;
            float f[8] = {pb[0].x, pb[0].y, pb[0].z, pb[0].w, pb[1].x, pb[1].y, pb[1].z, pb[1].w};
            uint32_t h[4], l[4];
#pragma unroll
            for (int q = 0; q < 4; ++q) split2(f[q * 2], f[q * 2 + 1], h[q], l[q]);
            *(uint4*)((char*)Bh + bb) = make_uint4(h[0], h[1], h[2], h[3]);
            *(uint4*)((char*)Bl + bb) = make_uint4(l[0], l[1], l[2], l[3]);
        }
        __syncthreads();
        if (c + 1 < FF / 32) {
            int k0 = (c + 1) * 32;
            const float* w2p = w2 + ((size_t)e * FF + k0 + bk) * HD + n_base + bn0;
#pragma unroll
            for (int q = 0; q < 2; ++q) {
                qh[q] = *(const uint4*)(ahp + k0 + ahalf * 16 + q * 8);
                ql[q] = *(const uint4*)(alp + k0 + ahalf * 16 + q * 8);
                pb[q] = *(const float4*)(w2p + q * 4);
            }
        }
#pragma unroll
        for (int ks = 0; ks < 2; ++ks) {
            uint32_t ah[2][4], al[2][4];
#pragma unroll
            for (int mf = 0; mf < 2; ++mf) {
                uint32_t ao = aoff + (uint32_t)mf * 16 * (ASTR * 2) + (uint32_t)ks * 32;
                ldsm4(ah[mf], sAh + ao);
                ldsm4(al[mf], sAl + ao);
            }
#pragma unroll
            for (int pr = 0; pr < 2; ++pr) {
                uint32_t o = boff + (uint32_t)ks * 16 * (BSTR * 2) + (uint32_t)pr * 32;
                uint32_t bh[4], bl[4];
                ldsm4t(bh, sBh + o); ldsm4t(bl, sBl + o);
#pragma unroll
                for (int sub = 0; sub < 2; ++sub) {
                    int nf = pr * 2 + sub;
#pragma unroll
                    for (int mf = 0; mf < 2; ++mf) {
                        mma16816(acc[mf][nf], ah[mf], bh + sub * 2);
                        mma16816(acc[mf][nf], ah[mf], bl + sub * 2);
                        mma16816(acc[mf][nf], al[mf], bh + sub * 2);
                    }
                }
            }
        }
    }

    // epilogue: weighted atomic scatter to out
#pragma unroll
    for (int mf = 0; mf < 2; ++mf) {
#pragma unroll
        for (int half = 0; half < 2; ++half) {
            int r = wm * 32 + mf * 16 + (lane >> 2) + half * 8;
            int grr = m_base + r;
            if (grr < cnt) {
                int tok = g_rowtok[e * CAP + grr];
                float w  = g_wslot[e * CAP + grr];
                float* op = out + (size_t)tok * HD + n_base + wn * 32 + (lane & 3) * 2;
#pragma unroll
                for (int nf = 0; nf < 4; ++nf) {
                    atomicAdd(op + nf * 8,     w * acc[mf][nf][half * 2]);
                    atomicAdd(op + nf * 8 + 1, w * acc[mf][nf][half * 2 + 1]);
                }
            }
        }
    }
}

// ---------------- 7) copy router logits into output tail ----------------
__global__ void copy_logits_kernel(float* __restrict__ dst) {
    int i = blockIdx.x * blockDim.x + threadIdx.x;
    int n = TOK * NE;
    for (; i < n; i += gridDim.x * blockDim.x) dst[i] = g_logits[i];
}

// ---------------- host launcher ----------------
extern "C" void kernel_launch(void* const* d_in, const int* in_sizes, int n_in,
                              void* d_out, int out_size) {
    const float* x  = (const float*)d_in[0];
    const float* wg = (const float*)d_in[1];
    const float* w1 = (const float*)d_in[2];
    const float* w3 = (const float*)d_in[3];
    const float* w2 = (const float*)d_in[4];
    float* out = (float*)d_out;

    router_kernel<<<TOK / RT, 256>>>(x, wg);          // launch 0 (also zeroes g_cnt)
    topk_kernel<<<(TOK + 255) / 256, 256>>>();        // launch 1
    dispatch_kernel<<<NA / 256, 256>>>();             // launch 2
    dim3 ga(FF / 64, CAP / 128, NE);
    gemm_a_mma<<<ga, 256>>>(x, w1, w3);               // launch 3 (profiled)
    zero_out_kernel<<<TOK * HD / 4 / 256, 256>>>((float4*)out);  // launch 4
    dim3 gb(HD / 64, CAP / 128, NE);
    gemm_b_mma<<<gb, 256>>>(w2, out);                 // launch 5

    if ((size_t)out_size >= (size_t)TOK * HD + (size_t)TOK * NE) {
        copy_logits_kernel<<<256, 256>>>(out + (size_t)TOK * HD);
    }
}

// round 6
// speedup vs baseline: 1.9525x; 1.6728x over previous
#include <cuda_runtime.h>
#include <cuda_bf16.h>
#include <cuda_fp16.h>
#include <math.h>
#include <stdint.h>

// Problem constants (B=2,S=2048,H=1024,E=64,K=8,F=512,cap=2.0)
#define TOK   4096
#define HD    1024
#define NE    64
#define KSEL  8
#define FF    512
#define NA    (TOK*KSEL)
#define CAP   1024

// ---------------- scratch (__device__ globals) ----------------
__device__ __align__(16) float g_logits[(size_t)TOK * NE];
__device__ int   g_sel[NA];
__device__ float g_wgt[NA];
__device__ int   g_rowtok[NE * CAP];
__device__ float g_wslot[NE * CAP];
__device__ int   g_cnt[NE];
__device__ __align__(16) __half g_act[(size_t)NE * CAP * FF];   // 64MB fp16

// ---------------- helpers ----------------
__device__ __forceinline__ uint32_t smem_u32(const void* p) {
    uint32_t a;
    asm("{ .reg .u64 t; cvta.to.shared.u64 t, %1; cvt.u32.u64 %0, t; }" : "=r"(a) : "l"(p));
    return a;
}
__device__ __forceinline__ void ldsm4(uint32_t* r, uint32_t addr) {
    asm volatile("ldmatrix.sync.aligned.m8n8.x4.shared.b16 {%0,%1,%2,%3}, [%4];"
                 : "=r"(r[0]), "=r"(r[1]), "=r"(r[2]), "=r"(r[3]) : "r"(addr));
}
__device__ __forceinline__ void ldsm4t(uint32_t* r, uint32_t addr) {
    asm volatile("ldmatrix.sync.aligned.m8n8.x4.trans.shared.b16 {%0,%1,%2,%3}, [%4];"
                 : "=r"(r[0]), "=r"(r[1]), "=r"(r[2]), "=r"(r[3]) : "r"(addr));
}
__device__ __forceinline__ void mma16816(float* c, const uint32_t* a, const uint32_t* b) {
    asm volatile("mma.sync.aligned.m16n8k16.row.col.f32.f16.f16.f32 "
                 "{%0,%1,%2,%3}, {%4,%5,%6,%7}, {%8,%9}, {%0,%1,%2,%3};"
                 : "+f"(c[0]), "+f"(c[1]), "+f"(c[2]), "+f"(c[3])
                 : "r"(a[0]), "r"(a[1]), "r"(a[2]), "r"(a[3]), "r"(b[0]), "r"(b[1]));
}
__device__ __forceinline__ uint32_t pkh(float a, float b) {
    __half2 h = __floats2half2_rn(a, b);
    return *(uint32_t*)&h;
}

// smem strides (half elements)
#define ASTR 40   // rows 80B = 20 words: banks 20r%32 distinct over 8 rows
#define BSTR 72   // rows 144B = 36 words: banks 4r%32 distinct over 8 rows

// ---------------- 1) router logits (+ zero g_cnt for dispatch) ----------------
#define RT 8
__global__ __launch_bounds__(256) void router_kernel(const float* __restrict__ x,
                                                     const float* __restrict__ wg) {
    if (blockIdx.x == 0 && threadIdx.x < NE) g_cnt[threadIdx.x] = 0;
    __shared__ __align__(16) float xs[RT][HD];
    int t0 = blockIdx.x * RT;
    for (int i = threadIdx.x; i < RT * HD / 4; i += 256) {
        int r = i >> 8;
        int c = (i & 255) << 2;
        *(float4*)&xs[r][c] = *(const float4*)&x[(size_t)(t0 + r) * HD + c];
    }
    __syncthreads();
    int e  = threadIdx.x & 63;
    int tg = threadIdx.x >> 6;
    float acc0 = 0.f, acc1 = 0.f;
#pragma unroll 4
    for (int j = 0; j < HD; ++j) {
        float w = wg[(size_t)j * NE + e];
        acc0 += w * xs[tg * 2 + 0][j];
        acc1 += w * xs[tg * 2 + 1][j];
    }
    g_logits[(size_t)(t0 + tg * 2 + 0) * NE + e] = acc0;
    g_logits[(size_t)(t0 + tg * 2 + 1) * NE + e] = acc1;
}

// ---------------- 2) softmax + top-8 + renorm ----------------
__global__ void topk_kernel() {
    int t = blockIdx.x * blockDim.x + threadIdx.x;
    if (t >= TOK) return;
    const float* l = g_logits + (size_t)t * NE;
    float m = -INFINITY;
    for (int e = 0; e < NE; ++e) m = fmaxf(m, l[e]);
    float s = 0.f;
    for (int e = 0; e < NE; ++e) s += expf(l[e] - m);
    unsigned long long mask = 0ull;
    float wv[KSEL]; int se[KSEL];
    float wsum = 0.f;
    for (int k = 0; k < KSEL; ++k) {
        float best = -INFINITY; int be = 0;
        for (int e = 0; e < NE; ++e) {
            if ((mask >> e) & 1ull) continue;
            float v = l[e];
            if (v > best) { best = v; be = e; }
        }
        mask |= (1ull << be);
        float p = expf(best - m) / s;
        wv[k] = p; se[k] = be; wsum += p;
    }
    float inv = 1.f / wsum;
    for (int k = 0; k < KSEL; ++k) {
        g_sel[t * KSEL + k] = se[k];
        g_wgt[t * KSEL + k] = wv[k] * inv;
    }
}

// ---------------- 3) dispatch: atomic rank (order-free; no drops at CAP=2x) ----------------
__global__ __launch_bounds__(256) void dispatch_kernel() {
    int a = blockIdx.x * blockDim.x + threadIdx.x;
    if (a >= NA) return;
    int e = g_sel[a];
    int p = atomicAdd(&g_cnt[e], 1);
    if (p < CAP) {
        g_rowtok[e * CAP + p] = a >> 3;
        g_wslot[e * CAP + p]  = g_wgt[a];
    }
}

// ---------------- 4) zero output ----------------
__global__ void zero_out_kernel(float4* o) {
    int i = blockIdx.x * blockDim.x + threadIdx.x;
    o[i] = make_float4(0.f, 0.f, 0.f, 0.f);
}

// ---------------- 5) GEMM-A: act = silu(x@w1)*(x@w3)  [mma.sync fp16] ----------------
__global__ __launch_bounds__(256) void gemm_a_mma(const float* __restrict__ x,
                                                  const float* __restrict__ w1,
                                                  const float* __restrict__ w3) {
    __shared__ __align__(16) __half Ah[128 * ASTR];
    __shared__ __align__(16) __half B1h[32 * BSTR];
    __shared__ __align__(16) __half B3h[32 * BSTR];

    const int e = blockIdx.z;
    int cnt = g_cnt[e]; if (cnt > CAP) cnt = CAP;
    const int m_base = blockIdx.y * 128;
    if (m_base >= cnt) return;
    const int n_base = blockIdx.x * 64;

    const int tid = threadIdx.x, lane = tid & 31, wid = tid >> 5;
    const int wm = wid & 3, wn = wid >> 2;

    const int arow = tid >> 1, ahalf = tid & 1;          // A: 128 rows x 32 k
    int gr = m_base + arow; if (gr >= cnt) gr = cnt - 1;
    const float* xr = x + (size_t)g_rowtok[e * CAP + gr] * HD;
    const int bk = tid >> 3, bn0 = (tid & 7) * 8;        // B: 32 k x 64 n

    const uint32_t sAh = smem_u32(Ah);
    const uint32_t s1h = smem_u32(B1h), s3h = smem_u32(B3h);

    const uint32_t aoff = (uint32_t)(wm * 32 + (lane & 15)) * (ASTR * 2) + (uint32_t)(lane >> 4) * 16;
    const uint32_t boff = (uint32_t)(lane & 15) * (BSTR * 2) + (uint32_t)(lane >> 4) * 16 + (uint32_t)wn * 64;

    float acc1[2][4][4] = {}, acc3[2][4][4] = {};
    float4 pa[4], p1[2], p3[2];

    // prefetch chunk 0
    {
        const float* w1p = w1 + ((size_t)e * HD + bk) * FF + n_base + bn0;
        const float* w3p = w3 + ((size_t)e * HD + bk) * FF + n_base + bn0;
#pragma unroll
        for (int j = 0; j < 4; ++j) pa[j] = *(const float4*)(xr + ahalf * 16 + j * 4);
#pragma unroll
        for (int q = 0; q < 2; ++q) { p1[q] = *(const float4*)(w1p + q * 4); p3[q] = *(const float4*)(w3p + q * 4); }
    }

    for (int c = 0; c < HD / 32; ++c) {
        __syncthreads();
        // store prefetched regs -> smem (fp16)
        {
            uint32_t ab = (uint32_t)arow * (ASTR * 2) + (uint32_t)ahalf * 32;
#pragma unroll
            for (int j = 0; j < 4; ++j)
                *(uint2*)((char*)Ah + ab + j * 8) = make_uint2(pkh(pa[j].x, pa[j].y), pkh(pa[j].z, pa[j].w));
            uint32_t bb = (uint32_t)bk * (BSTR * 2) + (uint32_t)bn0 * 2;
            *(uint4*)((char*)B1h + bb) = make_uint4(pkh(p1[0].x, p1[0].y), pkh(p1[0].z, p1[0].w),
                                                    pkh(p1[1].x, p1[1].y), pkh(p1[1].z, p1[1].w));
            *(uint4*)((char*)B3h + bb) = make_uint4(pkh(p3[0].x, p3[0].y), pkh(p3[0].z, p3[0].w),
                                                    pkh(p3[1].x, p3[1].y), pkh(p3[1].z, p3[1].w));
        }
        __syncthreads();
        // prefetch next chunk
        if (c + 1 < HD / 32) {
            int k0 = (c + 1) * 32;
            const float* w1p = w1 + ((size_t)e * HD + k0 + bk) * FF + n_base + bn0;
            const float* w3p = w3 + ((size_t)e * HD + k0 + bk) * FF + n_base + bn0;
#pragma unroll
            for (int j = 0; j < 4; ++j) pa[j] = *(const float4*)(xr + k0 + ahalf * 16 + j * 4);
#pragma unroll
            for (int q = 0; q < 2; ++q) { p1[q] = *(const float4*)(w1p + q * 4); p3[q] = *(const float4*)(w3p + q * 4); }
        }
        // compute: 2 k16 steps
#pragma unroll
        for (int ks = 0; ks < 2; ++ks) {
            uint32_t ah[2][4];
#pragma unroll
            for (int mf = 0; mf < 2; ++mf)
                ldsm4(ah[mf], sAh + aoff + (uint32_t)mf * 16 * (ASTR * 2) + (uint32_t)ks * 32);
#pragma unroll
            for (int pr = 0; pr < 2; ++pr) {
                uint32_t o = boff + (uint32_t)ks * 16 * (BSTR * 2) + (uint32_t)pr * 32;
                uint32_t b1[4], b3[4];
                ldsm4t(b1, s1h + o); ldsm4t(b3, s3h + o);
#pragma unroll
                for (int sub = 0; sub < 2; ++sub) {
                    int nf = pr * 2 + sub;
#pragma unroll
                    for (int mf = 0; mf < 2; ++mf) {
                        mma16816(acc1[mf][nf], ah[mf], b1 + sub * 2);
                        mma16816(acc3[mf][nf], ah[mf], b3 + sub * 2);
                    }
                }
            }
        }
    }

    // epilogue: silu(g)*u -> fp16 to g_act
#pragma unroll
    for (int mf = 0; mf < 2; ++mf) {
#pragma unroll
        for (int half = 0; half < 2; ++half) {
            int r = wm * 32 + mf * 16 + (lane >> 2) + half * 8;
            int grr = m_base + r;
            if (grr < cnt) {
                size_t rb = ((size_t)e * CAP + grr) * FF + n_base + wn * 32 + (lane & 3) * 2;
#pragma unroll
                for (int nf = 0; nf < 4; ++nf) {
                    float g0 = acc1[mf][nf][half * 2],     u0 = acc3[mf][nf][half * 2];
                    float g1 = acc1[mf][nf][half * 2 + 1], u1 = acc3[mf][nf][half * 2 + 1];
                    float a0 = (g0 / (1.f + expf(-g0))) * u0;
                    float a1 = (g1 / (1.f + expf(-g1))) * u1;
                    *(uint32_t*)&g_act[rb + nf * 8] = pkh(a0, a1);
                }
            }
        }
    }
}

// ---------------- 6) GEMM-B: out += w * (act @ w2)  [mma.sync fp16 + scatter] ----------------
__global__ __launch_bounds__(256) void gemm_b_mma(const float* __restrict__ w2,
                                                  float* __restrict__ out) {
    __shared__ __align__(16) __half Ah[128 * ASTR];
    __shared__ __align__(16) __half Bh[32 * BSTR];

    const int e = blockIdx.z;
    int cnt = g_cnt[e]; if (cnt > CAP) cnt = CAP;
    const int m_base = blockIdx.y * 128;
    if (m_base >= cnt) return;
    const int n_base = blockIdx.x * 64;

    const int tid = threadIdx.x, lane = tid & 31, wid = tid >> 5;
    const int wm = wid & 3, wn = wid >> 2;

    const int arow = tid >> 1, ahalf = tid & 1;
    int gr = m_base + arow; if (gr >= cnt) gr = cnt - 1;
    const __half* ahp = g_act + ((size_t)e * CAP + gr) * FF;
    const int bk = tid >> 3, bn0 = (tid & 7) * 8;

    const uint32_t sAh = smem_u32(Ah), sBh = smem_u32(Bh);
    const uint32_t aoff = (uint32_t)(wm * 32 + (lane & 15)) * (ASTR * 2) + (uint32_t)(lane >> 4) * 16;
    const uint32_t boff = (uint32_t)(lane & 15) * (BSTR * 2) + (uint32_t)(lane >> 4) * 16 + (uint32_t)wn * 64;

    float acc[2][4][4] = {};
    uint4 qh[2];
    float4 pb[2];

    {
        const float* w2p = w2 + ((size_t)e * FF + bk) * HD + n_base + bn0;
#pragma unroll
        for (int q = 0; q < 2; ++q) {
            qh[q] = *(const uint4*)(ahp + ahalf * 16 + q * 8);
            pb[q] = *(const float4*)(w2p + q * 4);
        }
    }

    for (int c = 0; c < FF / 32; ++c) {
        __syncthreads();
        {
            uint32_t ab = (uint32_t)arow * (ASTR * 2) + (uint32_t)ahalf * 32;
#pragma unroll
            for (int q = 0; q < 2; ++q) *(uint4*)((char*)Ah + ab + q * 16) = qh[q];
            uint32_t bb = (uint32_t)bk * (BSTR * 2) + (uint32_t)bn0 * 2;
            *(uint4*)((char*)Bh + bb) = make_uint4(pkh(pb[0].x, pb[0].y), pkh(pb[0].z, pb[0].w),
                                                   pkh(pb[1].x, pb[1].y), pkh(pb[1].z, pb[1].w));
        }
        __syncthreads();
        if (c + 1 < FF / 32) {
            int k0 = (c + 1) * 32;
            const float* w2p = w2 + ((size_t)e * FF + k0 + bk) * HD + n_base + bn0;
#pragma unroll
            for (int q = 0; q < 2; ++q) {
                qh[q] = *(const uint4*)(ahp + k0 + ahalf * 16 + q * 8);
                pb[q] = *(const float4*)(w2p + q * 4);
            }
        }
#pragma unroll
        for (int ks = 0; ks < 2; ++ks) {
            uint32_t ah[2][4];
#pragma unroll
            for (int mf = 0; mf < 2; ++mf)
                ldsm4(ah[mf], sAh + aoff + (uint32_t)mf * 16 * (ASTR * 2) + (uint32_t)ks * 32);
#pragma unroll
            for (int pr = 0; pr < 2; ++pr) {
                uint32_t o = boff + (uint32_t)ks * 16 * (BSTR * 2) + (uint32_t)pr * 32;
                uint32_t bh[4];
                ldsm4t(bh, sBh + o);
#pragma unroll
                for (int sub = 0; sub < 2; ++sub) {
                    int nf = pr * 2 + sub;
#pragma unroll
                    for (int mf = 0; mf < 2; ++mf)
                        mma16816(acc[mf][nf], ah[mf], bh + sub * 2);
                }
            }
        }
    }

    // epilogue: weighted atomic scatter to out
#pragma unroll
    for (int mf = 0; mf < 2; ++mf) {
#pragma unroll
        for (int half = 0; half < 2; ++half) {
            int r = wm * 32 + mf * 16 + (lane >> 2) + half * 8;
            int grr = m_base + r;
            if (grr < cnt) {
                int tok = g_rowtok[e * CAP + grr];
                float w  = g_wslot[e * CAP + grr];
                float* op = out + (size_t)tok * HD + n_base + wn * 32 + (lane & 3) * 2;
#pragma unroll
                for (int nf = 0; nf < 4; ++nf) {
                    atomicAdd(op + nf * 8,     w * acc[mf][nf][half * 2]);
                    atomicAdd(op + nf * 8 + 1, w * acc[mf][nf][half * 2 + 1]);
                }
            }
        }
    }
}

// ---------------- 7) copy router logits into output tail ----------------
__global__ void copy_logits_kernel(float* __restrict__ dst) {
    int i = blockIdx.x * blockDim.x + threadIdx.x;
    int n = TOK * NE;
    for (; i < n; i += gridDim.x * blockDim.x) dst[i] = g_logits[i];
}

// ---------------- host launcher ----------------
extern "C" void kernel_launch(void* const* d_in, const int* in_sizes, int n_in,
                              void* d_out, int out_size) {
    const float* x  = (const float*)d_in[0];
    const float* wg = (const float*)d_in[1];
    const float* w1 = (const float*)d_in[2];
    const float* w3 = (const float*)d_in[3];
    const float* w2 = (const float*)d_in[4];
    float* out = (float*)d_out;

    router_kernel<<<TOK / RT, 256>>>(x, wg);          // launch 0 (also zeroes g_cnt)
    topk_kernel<<<(TOK + 255) / 256, 256>>>();        // launch 1
    dispatch_kernel<<<NA / 256, 256>>>();             // launch 2
    dim3 ga(FF / 64, CAP / 128, NE);
    gemm_a_mma<<<ga, 256>>>(x, w1, w3);               // launch 3 (profiled)
    zero_out_kernel<<<TOK * HD / 4 / 256, 256>>>((float4*)out);  // launch 4
    dim3 gb(HD / 64, CAP / 128, NE);
    gemm_b_mma<<<gb, 256>>>(w2, out);                 // launch 5

    if ((size_t)out_size >= (size_t)TOK * HD + (size_t)TOK * NE) {
        copy_logits_kernel<<<256, 256>>>(out + (size_t)TOK * HD);
    }
}

// round 7
// speedup vs baseline: 2.2939x; 1.1748x over previous
#include <cuda_runtime.h>
#include <cuda_fp16.h>
#include <math.h>
#include <stdint.h>

// Problem constants (B=2,S=2048,H=1024,E=64,K=8,F=512,cap=2.0)
#define TOK   4096
#define HD    1024
#define NE    64
#define KSEL  8
#define FF    512
#define NA    (TOK*KSEL)
#define CAP   1024

// ---------------- scratch (__device__ globals) ----------------
__device__ __align__(16) float g_logits[(size_t)TOK * NE];
__device__ int   g_sel[NA];
__device__ float g_wgt[NA];
__device__ int   g_rowtok[NE * CAP];
__device__ float g_wslot[NE * CAP];
__device__ int   g_cnt[NE];
__device__ __align__(16) __half g_xh [(size_t)TOK * HD];            // 8MB
__device__ __align__(16) __half g_w1h[(size_t)NE * HD * FF];        // 64MB
__device__ __align__(16) __half g_w3h[(size_t)NE * HD * FF];        // 64MB
__device__ __align__(16) __half g_w2h[(size_t)NE * FF * HD];        // 64MB
__device__ __align__(16) __half g_act[(size_t)NE * CAP * FF];       // 64MB

// ---------------- helpers ----------------
__device__ __forceinline__ uint32_t smem_u32(const void* p) {
    uint32_t a;
    asm("{ .reg .u64 t; cvta.to.shared.u64 t, %1; cvt.u32.u64 %0, t; }" : "=r"(a) : "l"(p));
    return a;
}
__device__ __forceinline__ void cpa16(uint32_t s, const void* g) {
    asm volatile("cp.async.cg.shared.global [%0], [%1], 16;" :: "r"(s), "l"(g));
}
#define CP_COMMIT() asm volatile("cp.async.commit_group;" ::: "memory")
#define CP_WAIT1()  asm volatile("cp.async.wait_group 1;" ::: "memory")
__device__ __forceinline__ void ldsm4(uint32_t* r, uint32_t addr) {
    asm volatile("ldmatrix.sync.aligned.m8n8.x4.shared.b16 {%0,%1,%2,%3}, [%4];"
                 : "=r"(r[0]), "=r"(r[1]), "=r"(r[2]), "=r"(r[3]) : "r"(addr));
}
__device__ __forceinline__ void ldsm4t(uint32_t* r, uint32_t addr) {
    asm volatile("ldmatrix.sync.aligned.m8n8.x4.trans.shared.b16 {%0,%1,%2,%3}, [%4];"
                 : "=r"(r[0]), "=r"(r[1]), "=r"(r[2]), "=r"(r[3]) : "r"(addr));
}
__device__ __forceinline__ void mma16816(float* c, const uint32_t* a, const uint32_t* b) {
    asm volatile("mma.sync.aligned.m16n8k16.row.col.f32.f16.f16.f32 "
                 "{%0,%1,%2,%3}, {%4,%5,%6,%7}, {%8,%9}, {%0,%1,%2,%3};"
                 : "+f"(c[0]), "+f"(c[1]), "+f"(c[2]), "+f"(c[3])
                 : "r"(a[0]), "r"(a[1]), "r"(a[2]), "r"(a[3]), "r"(b[0]), "r"(b[1]));
}
__device__ __forceinline__ uint32_t pkh(float a, float b) {
    __half2 h = __floats2half2_rn(a, b);
    return *(uint32_t*)&h;
}

// smem layouts (bytes). A row stride 80B (conflict-free, 16B multiple);
// gemm_a B stride 272B; gemm_b B stride 528B (both 4i-mod-32 bank walks).
#define GA_A(s)   ((s) * 10240)
#define GA_B1(s)  (30720 + (s) * 8704)
#define GA_B3(s)  (56832 + (s) * 8704)
#define GA_TOTAL  82944
#define GB_A(s)   ((s) * 10240)
#define GB_B(s)   (30720 + (s) * 16896)
#define GB_TOTAL  81408

// ---------------- 1) router logits + fp16 conversions (fused) ----------------
#define RT 8
#define RB (TOK / RT)          // 512 router blocks
#define CVB 1536               // conversion blocks
__global__ __launch_bounds__(256) void router_cvt_kernel(const float* __restrict__ x,
                                                         const float* __restrict__ wg,
                                                         const float* __restrict__ w1,
                                                         const float* __restrict__ w3,
                                                         const float* __restrict__ w2) {
    if (blockIdx.x >= RB) {
        // weight conversion: grid-stride over E*H*F float4 elements of each weight
        const size_t N4 = (size_t)NE * HD * FF / 4;
        size_t i = (size_t)(blockIdx.x - RB) * 256 + threadIdx.x;
        size_t stride = (size_t)CVB * 256;
        for (; i < N4; i += stride) {
            float4 v = ((const float4*)w1)[i];
            ((uint2*)g_w1h)[i] = make_uint2(pkh(v.x, v.y), pkh(v.z, v.w));
            v = ((const float4*)w3)[i];
            ((uint2*)g_w3h)[i] = make_uint2(pkh(v.x, v.y), pkh(v.z, v.w));
            v = ((const float4*)w2)[i];
            ((uint2*)g_w2h)[i] = make_uint2(pkh(v.x, v.y), pkh(v.z, v.w));
        }
        return;
    }
    if (blockIdx.x == 0 && threadIdx.x < NE) g_cnt[threadIdx.x] = 0;
    __shared__ __align__(16) float xs[RT][HD];
    int t0 = blockIdx.x * RT;
    for (int i = threadIdx.x; i < RT * HD / 4; i += 256) {
        int r = i >> 8;
        int c = (i & 255) << 2;
        float4 v = *(const float4*)&x[(size_t)(t0 + r) * HD + c];
        *(float4*)&xs[r][c] = v;
        *(uint2*)&g_xh[(size_t)(t0 + r) * HD + c] = make_uint2(pkh(v.x, v.y), pkh(v.z, v.w));
    }
    __syncthreads();
    int e  = threadIdx.x & 63;
    int tg = threadIdx.x >> 6;
    float acc0 = 0.f, acc1 = 0.f;
#pragma unroll 4
    for (int j = 0; j < HD; ++j) {
        float w = wg[(size_t)j * NE + e];
        acc0 += w * xs[tg * 2 + 0][j];
        acc1 += w * xs[tg * 2 + 1][j];
    }
    g_logits[(size_t)(t0 + tg * 2 + 0) * NE + e] = acc0;
    g_logits[(size_t)(t0 + tg * 2 + 1) * NE + e] = acc1;
}

// ---------------- 2) softmax + top-8 + renorm ----------------
__global__ void topk_kernel() {
    int t = blockIdx.x * blockDim.x + threadIdx.x;
    if (t >= TOK) return;
    const float* l = g_logits + (size_t)t * NE;
    float m = -INFINITY;
    for (int e = 0; e < NE; ++e) m = fmaxf(m, l[e]);
    float s = 0.f;
    for (int e = 0; e < NE; ++e) s += expf(l[e] - m);
    unsigned long long mask = 0ull;
    float wv[KSEL]; int se[KSEL];
    float wsum = 0.f;
    for (int k = 0; k < KSEL; ++k) {
        float best = -INFINITY; int be = 0;
        for (int e = 0; e < NE; ++e) {
            if ((mask >> e) & 1ull) continue;
            float v = l[e];
            if (v > best) { best = v; be = e; }
        }
        mask |= (1ull << be);
        float p = expf(best - m) / s;
        wv[k] = p; se[k] = be; wsum += p;
    }
    float inv = 1.f / wsum;
    for (int k = 0; k < KSEL; ++k) {
        g_sel[t * KSEL + k] = se[k];
        g_wgt[t * KSEL + k] = wv[k] * inv;
    }
}

// ---------------- 3) dispatch: atomic rank (order-free; no drops at CAP=2x) ----------------
__global__ __launch_bounds__(256) void dispatch_kernel() {
    int a = blockIdx.x * blockDim.x + threadIdx.x;
    if (a >= NA) return;
    int e = g_sel[a];
    int p = atomicAdd(&g_cnt[e], 1);
    if (p < CAP) {
        g_rowtok[e * CAP + p] = a >> 3;
        g_wslot[e * CAP + p]  = g_wgt[a];
    }
}

// ---------------- 4) zero output ----------------
__global__ void zero_out_kernel(float4* o) {
    int i = blockIdx.x * blockDim.x + threadIdx.x;
    o[i] = make_float4(0.f, 0.f, 0.f, 0.f);
}

// ---------------- 5) GEMM-A: act = silu(x@w1)*(x@w3)  [fp16 mma, cp.async x3 stages] ----------------
// block 128m x 128n x BK32; 8 warps = 2m x 4n; warp tile 64x32
__global__ __launch_bounds__(256) void gemm_a_mma() {
    extern __shared__ char smc[];
    const uint32_t sb = smem_u32(smc);

    const int e = blockIdx.z;
    int cnt = g_cnt[e]; if (cnt > CAP) cnt = CAP;
    const int m_base = blockIdx.y * 128;
    if (m_base >= cnt) return;
    const int n_base = blockIdx.x * 128;

    const int tid = threadIdx.x, lane = tid & 31, wid = tid >> 5;
    const int wm = wid >> 2, wn = wid & 3;

    // cp.async mappings
    const int arow = tid >> 1, ahalf = tid & 1;
    int gr = m_base + arow; if (gr >= cnt) gr = cnt - 1;
    const __half* xr = g_xh + (size_t)g_rowtok[e * CAP + gr] * HD + ahalf * 16;
    const int bk = tid >> 3, bc0 = tid & 7;

    const uint32_t aoff = (uint32_t)(wm * 64 + (lane & 15)) * 80 + (uint32_t)(lane >> 4) * 16;
    const uint32_t boff = (uint32_t)(lane & 15) * 272 + (uint32_t)(lane >> 4) * 16 + (uint32_t)wn * 64;

    float acc1[4][4][4] = {}, acc3[4][4][4] = {};

    auto issue = [&](int cc) {
        int s = cc % 3, k0 = cc * 32;
        uint32_t ad = sb + GA_A(s) + (uint32_t)arow * 80 + (uint32_t)ahalf * 32;
        cpa16(ad, xr + k0);
        cpa16(ad + 16, xr + k0 + 8);
        size_t ro = ((size_t)e * HD + k0 + bk) * FF + n_base;
        uint32_t bd1 = sb + GA_B1(s) + (uint32_t)bk * 272;
        uint32_t bd3 = sb + GA_B3(s) + (uint32_t)bk * 272;
        cpa16(bd1 + bc0 * 16,        g_w1h + ro + bc0 * 8);
        cpa16(bd1 + (bc0 + 8) * 16,  g_w1h + ro + (bc0 + 8) * 8);
        cpa16(bd3 + bc0 * 16,        g_w3h + ro + bc0 * 8);
        cpa16(bd3 + (bc0 + 8) * 16,  g_w3h + ro + (bc0 + 8) * 8);
    };

    issue(0); CP_COMMIT();
    issue(1); CP_COMMIT();

    for (int c = 0; c < HD / 32; ++c) {
        CP_WAIT1();
        __syncthreads();
        if (c + 2 < HD / 32) issue(c + 2);
        CP_COMMIT();
        const int s = c % 3;
        const uint32_t aS = sb + GA_A(s), b1S = sb + GA_B1(s), b3S = sb + GA_B3(s);
#pragma unroll
        for (int ks = 0; ks < 2; ++ks) {
            uint32_t a[4][4];
#pragma unroll
            for (int mf = 0; mf < 4; ++mf)
                ldsm4(a[mf], aS + aoff + (uint32_t)mf * (16 * 80) + (uint32_t)ks * 32);
            uint32_t b1[8], b3[8];
            uint32_t bo = boff + (uint32_t)ks * (16 * 272);
            ldsm4t(b1,     b1S + bo);
            ldsm4t(b1 + 4, b1S + bo + 32);
            ldsm4t(b3,     b3S + bo);
            ldsm4t(b3 + 4, b3S + bo + 32);
#pragma unroll
            for (int nf = 0; nf < 4; ++nf) {
                const uint32_t* f1 = b1 + (nf >> 1) * 4 + (nf & 1) * 2;
                const uint32_t* f3 = b3 + (nf >> 1) * 4 + (nf & 1) * 2;
#pragma unroll
                for (int mf = 0; mf < 4; ++mf) {
                    mma16816(acc1[mf][nf], a[mf], f1);
                    mma16816(acc3[mf][nf], a[mf], f3);
                }
            }
        }
    }

    // epilogue: silu(g)*u -> fp16 act
#pragma unroll
    for (int mf = 0; mf < 4; ++mf) {
#pragma unroll
        for (int half = 0; half < 2; ++half) {
            int r = wm * 64 + mf * 16 + (lane >> 2) + half * 8;
            int grr = m_base + r;
            if (grr < cnt) {
                size_t rb = ((size_t)e * CAP + grr) * FF + n_base + wn * 32 + (lane & 3) * 2;
#pragma unroll
                for (int nf = 0; nf < 4; ++nf) {
                    float g0 = acc1[mf][nf][half * 2],     u0 = acc3[mf][nf][half * 2];
                    float g1 = acc1[mf][nf][half * 2 + 1], u1 = acc3[mf][nf][half * 2 + 1];
                    float a0 = (g0 / (1.f + expf(-g0))) * u0;
                    float a1 = (g1 / (1.f + expf(-g1))) * u1;
                    *(uint32_t*)&g_act[rb + nf * 8] = pkh(a0, a1);
                }
            }
        }
    }
}

// ---------------- 6) GEMM-B: out += w * (act @ w2)  [fp16 mma, cp.async, scatter] ----------------
// block 128m x 256n x BK32; 8 warps = 2m x 4n; warp tile 64x64
__global__ __launch_bounds__(256) void gemm_b_mma(float* __restrict__ out) {
    extern __shared__ char smc[];
    const uint32_t sb = smem_u32(smc);

    const int e = blockIdx.z;
    int cnt = g_cnt[e]; if (cnt > CAP) cnt = CAP;
    const int m_base = blockIdx.y * 128;
    if (m_base >= cnt) return;
    const int n_base = blockIdx.x * 256;

    const int tid = threadIdx.x, lane = tid & 31, wid = tid >> 5;
    const int wm = wid >> 2, wn = wid & 3;

    const int arow = tid >> 1, ahalf = tid & 1;
    int gr = m_base + arow; if (gr >= cnt) gr = cnt - 1;
    const __half* ar = g_act + ((size_t)e * CAP + gr) * FF + ahalf * 16;
    const int bk = tid >> 3, bc0 = tid & 7;

    const uint32_t aoff = (uint32_t)(wm * 64 + (lane & 15)) * 80 + (uint32_t)(lane >> 4) * 16;
    const uint32_t boff = (uint32_t)(lane & 15) * 528 + (uint32_t)(lane >> 4) * 16 + (uint32_t)wn * 128;

    float acc[4][8][4] = {};

    auto issue = [&](int cc) {
        int s = cc % 3, k0 = cc * 32;
        uint32_t ad = sb + GB_A(s) + (uint32_t)arow * 80 + (uint32_t)ahalf * 32;
        cpa16(ad, ar + k0);
        cpa16(ad + 16, ar + k0 + 8);
        const __half* bsrc = g_w2h + ((size_t)e * FF + k0 + bk) * HD + n_base;
        uint32_t bd = sb + GB_B(s) + (uint32_t)bk * 528;
#pragma unroll
        for (int q = 0; q < 4; ++q)
            cpa16(bd + (bc0 + q * 8) * 16, bsrc + (bc0 + q * 8) * 8);
    };

    issue(0); CP_COMMIT();
    issue(1); CP_COMMIT();

    for (int c = 0; c < FF / 32; ++c) {
        CP_WAIT1();
        __syncthreads();
        if (c + 2 < FF / 32) issue(c + 2);
        CP_COMMIT();
        const int s = c % 3;
        const uint32_t aS = sb + GB_A(s), bS = sb + GB_B(s);
#pragma unroll
        for (int ks = 0; ks < 2; ++ks) {
            uint32_t a[4][4];
#pragma unroll
            for (int mf = 0; mf < 4; ++mf)
                ldsm4(a[mf], aS + aoff + (uint32_t)mf * (16 * 80) + (uint32_t)ks * 32);
            uint32_t b[16];
            uint32_t bo = boff + (uint32_t)ks * (16 * 528);
#pragma unroll
            for (int pr = 0; pr < 4; ++pr)
                ldsm4t(b + pr * 4, bS + bo + (uint32_t)pr * 32);
#pragma unroll
            for (int nf = 0; nf < 8; ++nf) {
                const uint32_t* fb = b + (nf >> 1) * 4 + (nf & 1) * 2;
#pragma unroll
                for (int mf = 0; mf < 4; ++mf)
                    mma16816(acc[mf][nf], a[mf], fb);
            }
        }
    }

    // epilogue: weighted atomic scatter
#pragma unroll
    for (int mf = 0; mf < 4; ++mf) {
#pragma unroll
        for (int half = 0; half < 2; ++half) {
            int r = wm * 64 + mf * 16 + (lane >> 2) + half * 8;
            int grr = m_base + r;
            if (grr < cnt) {
                int tok = g_rowtok[e * CAP + grr];
                float w  = g_wslot[e * CAP + grr];
                float* op = out + (size_t)tok * HD + n_base + wn * 64 + (lane & 3) * 2;
#pragma unroll
                for (int nf = 0; nf < 8; ++nf) {
                    atomicAdd(op + nf * 8,     w * acc[mf][nf][half * 2]);
                    atomicAdd(op + nf * 8 + 1, w * acc[mf][nf][half * 2 + 1]);
                }
            }
        }
    }
}

// ---------------- 7) copy router logits into output tail ----------------
__global__ void copy_logits_kernel(float* __restrict__ dst) {
    int i = blockIdx.x * blockDim.x + threadIdx.x;
    int n = TOK * NE;
    for (; i < n; i += gridDim.x * blockDim.x) dst[i] = g_logits[i];
}

// ---------------- host launcher ----------------
extern "C" void kernel_launch(void* const* d_in, const int* in_sizes, int n_in,
                              void* d_out, int out_size) {
    const float* x  = (const float*)d_in[0];
    const float* wg = (const float*)d_in[1];
    const float* w1 = (const float*)d_in[2];
    const float* w3 = (const float*)d_in[3];
    const float* w2 = (const float*)d_in[4];
    float* out = (float*)d_out;

    cudaFuncSetAttribute(gemm_a_mma, cudaFuncAttributeMaxDynamicSharedMemorySize, GA_TOTAL);
    cudaFuncSetAttribute(gemm_b_mma, cudaFuncAttributeMaxDynamicSharedMemorySize, GB_TOTAL);

    router_cvt_kernel<<<RB + CVB, 256>>>(x, wg, w1, w3, w2);   // 0: router + fp16 converts
    topk_kernel<<<(TOK + 255) / 256, 256>>>();                 // 1
    dispatch_kernel<<<NA / 256, 256>>>();                      // 2
    dim3 ga(FF / 128, CAP / 128, NE);                          // (4, 8, 64)
    gemm_a_mma<<<ga, 256, GA_TOTAL>>>();                       // 3 (profiled)
    zero_out_kernel<<<TOK * HD / 4 / 256, 256>>>((float4*)out);// 4
    dim3 gb(HD / 256, CAP / 128, NE);                          // (4, 8, 64)
    gemm_b_mma<<<gb, 256, GB_TOTAL>>>(out);                    // 5

    if ((size_t)out_size >= (size_t)TOK * HD + (size_t)TOK * NE) {
        copy_logits_kernel<<<256, 256>>>(out + (size_t)TOK * HD);
    }
}

// round 8
// speedup vs baseline: 2.5451x; 1.1095x over previous
#include <cuda_runtime.h>
#include <cuda_fp16.h>
#include <math.h>
#include <stdint.h>

// Problem constants (B=2,S=2048,H=1024,E=64,K=8,F=512,cap=2.0)
#define TOK   4096
#define HD    1024
#define NE    64
#define KSEL  8
#define FF    512
#define NA    (TOK*KSEL)
#define CAP   1024

// ---------------- scratch (__device__ globals) ----------------
__device__ __align__(16) float g_logits[(size_t)TOK * NE];
__device__ int   g_sel[NA];
__device__ float g_wgt[NA];
__device__ int   g_rowtok[NE * CAP];
__device__ float g_wslot[NE * CAP];
__device__ int   g_cnt[NE];
__device__ __align__(16) __half g_xh [(size_t)TOK * HD];            // 8MB
__device__ __align__(16) __half g_w1h[(size_t)NE * HD * FF];        // 64MB
__device__ __align__(16) __half g_w3h[(size_t)NE * HD * FF];        // 64MB
__device__ __align__(16) __half g_w2h[(size_t)NE * FF * HD];        // 64MB
__device__ __align__(16) __half g_act[(size_t)NE * CAP * FF];       // 64MB

// ---------------- helpers ----------------
__device__ __forceinline__ uint32_t smem_u32(const void* p) {
    uint32_t a;
    asm("{ .reg .u64 t; cvta.to.shared.u64 t, %1; cvt.u32.u64 %0, t; }" : "=r"(a) : "l"(p));
    return a;
}
__device__ __forceinline__ void cpa16(uint32_t s, const void* g) {
    asm volatile("cp.async.cg.shared.global [%0], [%1], 16;" :: "r"(s), "l"(g));
}
#define CP_COMMIT() asm volatile("cp.async.commit_group;" ::: "memory")
#define CP_WAIT1()  asm volatile("cp.async.wait_group 1;" ::: "memory")
__device__ __forceinline__ void ldsm4(uint32_t* r, uint32_t addr) {
    asm volatile("ldmatrix.sync.aligned.m8n8.x4.shared.b16 {%0,%1,%2,%3}, [%4];"
                 : "=r"(r[0]), "=r"(r[1]), "=r"(r[2]), "=r"(r[3]) : "r"(addr));
}
__device__ __forceinline__ void ldsm4t(uint32_t* r, uint32_t addr) {
    asm volatile("ldmatrix.sync.aligned.m8n8.x4.trans.shared.b16 {%0,%1,%2,%3}, [%4];"
                 : "=r"(r[0]), "=r"(r[1]), "=r"(r[2]), "=r"(r[3]) : "r"(addr));
}
__device__ __forceinline__ void mma16816(float* c, const uint32_t* a, const uint32_t* b) {
    asm volatile("mma.sync.aligned.m16n8k16.row.col.f32.f16.f16.f32 "
                 "{%0,%1,%2,%3}, {%4,%5,%6,%7}, {%8,%9}, {%0,%1,%2,%3};"
                 : "+f"(c[0]), "+f"(c[1]), "+f"(c[2]), "+f"(c[3])
                 : "r"(a[0]), "r"(a[1]), "r"(a[2]), "r"(a[3]), "r"(b[0]), "r"(b[1]));
}
__device__ __forceinline__ uint32_t pkh(float a, float b) {
    __half2 h = __floats2half2_rn(a, b);
    return *(uint32_t*)&h;
}

// smem layouts (bytes). A rows 80B; gemm_a B rows 144B; gemm_b B rows 272B.
#define GA_A(s)   ((s) * 10240)
#define GA_B1(s)  (30720 + (s) * 4608)
#define GA_B3(s)  (44544 + (s) * 4608)
#define GA_TOTAL  58368
#define GB_A(s)   ((s) * 10240)
#define GB_B(s)   (30720 + (s) * 8704)
#define GB_TOTAL  56832

// ---------------- 1) router logits + fp16 conversions (fused) ----------------
#define RT 8
#define RB (TOK / RT)          // 512 router blocks
#define CVB 1536               // conversion blocks
__global__ __launch_bounds__(256) void router_cvt_kernel(const float* __restrict__ x,
                                                         const float* __restrict__ wg,
                                                         const float* __restrict__ w1,
                                                         const float* __restrict__ w3,
                                                         const float* __restrict__ w2) {
    if (blockIdx.x >= RB) {
        const size_t N4 = (size_t)NE * HD * FF / 4;
        size_t i = (size_t)(blockIdx.x - RB) * 256 + threadIdx.x;
        size_t stride = (size_t)CVB * 256;
        for (; i < N4; i += stride) {
            float4 v = ((const float4*)w1)[i];
            ((uint2*)g_w1h)[i] = make_uint2(pkh(v.x, v.y), pkh(v.z, v.w));
            v = ((const float4*)w3)[i];
            ((uint2*)g_w3h)[i] = make_uint2(pkh(v.x, v.y), pkh(v.z, v.w));
            v = ((const float4*)w2)[i];
            ((uint2*)g_w2h)[i] = make_uint2(pkh(v.x, v.y), pkh(v.z, v.w));
        }
        return;
    }
    if (blockIdx.x == 0 && threadIdx.x < NE) g_cnt[threadIdx.x] = 0;
    __shared__ __align__(16) float xs[RT][HD];
    int t0 = blockIdx.x * RT;
    for (int i = threadIdx.x; i < RT * HD / 4; i += 256) {
        int r = i >> 8;
        int c = (i & 255) << 2;
        float4 v = *(const float4*)&x[(size_t)(t0 + r) * HD + c];
        *(float4*)&xs[r][c] = v;
        *(uint2*)&g_xh[(size_t)(t0 + r) * HD + c] = make_uint2(pkh(v.x, v.y), pkh(v.z, v.w));
    }
    __syncthreads();
    int e  = threadIdx.x & 63;
    int tg = threadIdx.x >> 6;
    float acc0 = 0.f, acc1 = 0.f;
#pragma unroll 4
    for (int j = 0; j < HD; ++j) {
        float w = wg[(size_t)j * NE + e];
        acc0 += w * xs[tg * 2 + 0][j];
        acc1 += w * xs[tg * 2 + 1][j];
    }
    g_logits[(size_t)(t0 + tg * 2 + 0) * NE + e] = acc0;
    g_logits[(size_t)(t0 + tg * 2 + 1) * NE + e] = acc1;
}

// ---------------- 2) softmax + top-8 + renorm ----------------
__global__ void topk_kernel() {
    int t = blockIdx.x * blockDim.x + threadIdx.x;
    if (t >= TOK) return;
    const float* l = g_logits + (size_t)t * NE;
    float m = -INFINITY;
    for (int e = 0; e < NE; ++e) m = fmaxf(m, l[e]);
    float s = 0.f;
    for (int e = 0; e < NE; ++e) s += expf(l[e] - m);
    unsigned long long mask = 0ull;
    float wv[KSEL]; int se[KSEL];
    float wsum = 0.f;
    for (int k = 0; k < KSEL; ++k) {
        float best = -INFINITY; int be = 0;
        for (int e = 0; e < NE; ++e) {
            if ((mask >> e) & 1ull) continue;
            float v = l[e];
            if (v > best) { best = v; be = e; }
        }
        mask |= (1ull << be);
        float p = expf(best - m) / s;
        wv[k] = p; se[k] = be; wsum += p;
    }
    float inv = 1.f / wsum;
    for (int k = 0; k < KSEL; ++k) {
        g_sel[t * KSEL + k] = se[k];
        g_wgt[t * KSEL + k] = wv[k] * inv;
    }
}

// ---------------- 3) dispatch: atomic rank (order-free; no drops at CAP=2x) ----------------
__global__ __launch_bounds__(256) void dispatch_kernel() {
    int a = blockIdx.x * blockDim.x + threadIdx.x;
    if (a >= NA) return;
    int e = g_sel[a];
    int p = atomicAdd(&g_cnt[e], 1);
    if (p < CAP) {
        g_rowtok[e * CAP + p] = a >> 3;
        g_wslot[e * CAP + p]  = g_wgt[a];
    }
}

// ---------------- 4) zero output ----------------
__global__ void zero_out_kernel(float4* o) {
    int i = blockIdx.x * blockDim.x + threadIdx.x;
    o[i] = make_float4(0.f, 0.f, 0.f, 0.f);
}

// ---------------- 5) GEMM-A: act = silu(x@w1)*(x@w3)  [fp16 mma, cp.async, 2 CTA/SM] ----------------
// block 128m x 64n x BK32; 8 warps = 4m x 2n; warp tile 32x32 (dual acc)
__global__ __launch_bounds__(256, 2) void gemm_a_mma() {
    extern __shared__ char smc[];
    const uint32_t sb = smem_u32(smc);

    const int e = blockIdx.z;
    int cnt = g_cnt[e]; if (cnt > CAP) cnt = CAP;
    const int m_base = blockIdx.y * 128;
    if (m_base >= cnt) return;
    const int n_base = blockIdx.x * 64;

    const int tid = threadIdx.x, lane = tid & 31, wid = tid >> 5;
    const int wm = wid >> 1, wn = wid & 1;

    const int arow = tid >> 1, ahalf = tid & 1;
    int gr = m_base + arow; if (gr >= cnt) gr = cnt - 1;
    const __half* xr = g_xh + (size_t)g_rowtok[e * CAP + gr] * HD + ahalf * 16;
    const int bk = tid >> 3, bc0 = tid & 7;   // B: 32 rows x 64n (128B = 8 chunks); 1 chunk per thread per matrix

    const uint32_t aoff = (uint32_t)(wm * 32 + (lane & 15)) * 80 + (uint32_t)(lane >> 4) * 16;
    const uint32_t boff = (uint32_t)(lane & 15) * 144 + (uint32_t)(lane >> 4) * 16 + (uint32_t)wn * 64;

    float acc1[2][4][4] = {}, acc3[2][4][4] = {};

    auto issue = [&](int cc) {
        int s = cc % 3, k0 = cc * 32;
        uint32_t ad = sb + GA_A(s) + (uint32_t)arow * 80 + (uint32_t)ahalf * 32;
        cpa16(ad, xr + k0);
        cpa16(ad + 16, xr + k0 + 8);
        size_t ro = ((size_t)e * HD + k0 + bk) * FF + n_base + bc0 * 8;
        cpa16(sb + GA_B1(s) + (uint32_t)bk * 144 + bc0 * 16, g_w1h + ro);
        cpa16(sb + GA_B3(s) + (uint32_t)bk * 144 + bc0 * 16, g_w3h + ro);
    };

    issue(0); CP_COMMIT();
    issue(1); CP_COMMIT();

    for (int c = 0; c < HD / 32; ++c) {
        CP_WAIT1();
        __syncthreads();
        if (c + 2 < HD / 32) issue(c + 2);
        CP_COMMIT();
        const int s = c % 3;
        const uint32_t aS = sb + GA_A(s), b1S = sb + GA_B1(s), b3S = sb + GA_B3(s);
#pragma unroll
        for (int ks = 0; ks < 2; ++ks) {
            uint32_t a[2][4];
#pragma unroll
            for (int mf = 0; mf < 2; ++mf)
                ldsm4(a[mf], aS + aoff + (uint32_t)mf * (16 * 80) + (uint32_t)ks * 32);
#pragma unroll
            for (int pr = 0; pr < 2; ++pr) {
                uint32_t o = boff + (uint32_t)ks * (16 * 144) + (uint32_t)pr * 32;
                uint32_t b1[4], b3[4];
                ldsm4t(b1, b1S + o); ldsm4t(b3, b3S + o);
#pragma unroll
                for (int sub = 0; sub < 2; ++sub) {
                    int nf = pr * 2 + sub;
#pragma unroll
                    for (int mf = 0; mf < 2; ++mf) {
                        mma16816(acc1[mf][nf], a[mf], b1 + sub * 2);
                        mma16816(acc3[mf][nf], a[mf], b3 + sub * 2);
                    }
                }
            }
        }
    }

    // epilogue: silu(g)*u -> fp16 act
#pragma unroll
    for (int mf = 0; mf < 2; ++mf) {
#pragma unroll
        for (int half = 0; half < 2; ++half) {
            int r = wm * 32 + mf * 16 + (lane >> 2) + half * 8;
            int grr = m_base + r;
            if (grr < cnt) {
                size_t rb = ((size_t)e * CAP + grr) * FF + n_base + wn * 32 + (lane & 3) * 2;
#pragma unroll
                for (int nf = 0; nf < 4; ++nf) {
                    float g0 = acc1[mf][nf][half * 2],     u0 = acc3[mf][nf][half * 2];
                    float g1 = acc1[mf][nf][half * 2 + 1], u1 = acc3[mf][nf][half * 2 + 1];
                    float a0 = (g0 / (1.f + expf(-g0))) * u0;
                    float a1 = (g1 / (1.f + expf(-g1))) * u1;
                    *(uint32_t*)&g_act[rb + nf * 8] = pkh(a0, a1);
                }
            }
        }
    }
}

// ---------------- 6) GEMM-B: out += w * (act @ w2)  [fp16 mma, cp.async, 2 CTA/SM, scatter] ----------------
// block 128m x 128n x BK32; 8 warps = 4m x 2n; warp tile 32x64
__global__ __launch_bounds__(256, 2) void gemm_b_mma(float* __restrict__ out) {
    extern __shared__ char smc[];
    const uint32_t sb = smem_u32(smc);

    const int e = blockIdx.z;
    int cnt = g_cnt[e]; if (cnt > CAP) cnt = CAP;
    const int m_base = blockIdx.y * 128;
    if (m_base >= cnt) return;
    const int n_base = blockIdx.x * 128;

    const int tid = threadIdx.x, lane = tid & 31, wid = tid >> 5;
    const int wm = wid >> 1, wn = wid & 1;

    const int arow = tid >> 1, ahalf = tid & 1;
    int gr = m_base + arow; if (gr >= cnt) gr = cnt - 1;
    const __half* ar = g_act + ((size_t)e * CAP + gr) * FF + ahalf * 16;
    const int bk = tid >> 3, bc0 = tid & 7;   // B: 32 rows x 128n (256B = 16 chunks); 2 per thread

    const uint32_t aoff = (uint32_t)(wm * 32 + (lane & 15)) * 80 + (uint32_t)(lane >> 4) * 16;
    const uint32_t boff = (uint32_t)(lane & 15) * 272 + (uint32_t)(lane >> 4) * 16 + (uint32_t)wn * 128;

    float acc[2][8][4] = {};

    auto issue = [&](int cc) {
        int s = cc % 3, k0 = cc * 32;
        uint32_t ad = sb + GB_A(s) + (uint32_t)arow * 80 + (uint32_t)ahalf * 32;
        cpa16(ad, ar + k0);
        cpa16(ad + 16, ar + k0 + 8);
        const __half* bsrc = g_w2h + ((size_t)e * FF + k0 + bk) * HD + n_base;
        uint32_t bd = sb + GB_B(s) + (uint32_t)bk * 272;
        cpa16(bd + bc0 * 16,       bsrc + bc0 * 8);
        cpa16(bd + (bc0 + 8) * 16, bsrc + (bc0 + 8) * 8);
    };

    issue(0); CP_COMMIT();
    issue(1); CP_COMMIT();

    for (int c = 0; c < FF / 32; ++c) {
        CP_WAIT1();
        __syncthreads();
        if (c + 2 < FF / 32) issue(c + 2);
        CP_COMMIT();
        const int s = c % 3;
        const uint32_t aS = sb + GB_A(s), bS = sb + GB_B(s);
#pragma unroll
        for (int ks = 0; ks < 2; ++ks) {
            uint32_t a[2][4];
#pragma unroll
            for (int mf = 0; mf < 2; ++mf)
                ldsm4(a[mf], aS + aoff + (uint32_t)mf * (16 * 80) + (uint32_t)ks * 32);
#pragma unroll
            for (int pr = 0; pr < 4; ++pr) {
                uint32_t b[4];
                ldsm4t(b, bS + boff + (uint32_t)ks * (16 * 272) + (uint32_t)pr * 32);
#pragma unroll
                for (int sub = 0; sub < 2; ++sub) {
                    int nf = pr * 2 + sub;
#pragma unroll
                    for (int mf = 0; mf < 2; ++mf)
                        mma16816(acc[mf][nf], a[mf], b + sub * 2);
                }
            }
        }
    }

    // epilogue: weighted atomic scatter
#pragma unroll
    for (int mf = 0; mf < 2; ++mf) {
#pragma unroll
        for (int half = 0; half < 2; ++half) {
            int r = wm * 32 + mf * 16 + (lane >> 2) + half * 8;
            int grr = m_base + r;
            if (grr < cnt) {
                int tok = g_rowtok[e * CAP + grr];
                float w  = g_wslot[e * CAP + grr];
                float* op = out + (size_t)tok * HD + n_base + wn * 64 + (lane & 3) * 2;
#pragma unroll
                for (int nf = 0; nf < 8; ++nf) {
                    atomicAdd(op + nf * 8,     w * acc[mf][nf][half * 2]);
                    atomicAdd(op + nf * 8 + 1, w * acc[mf][nf][half * 2 + 1]);
                }
            }
        }
    }
}

// ---------------- 7) copy router logits into output tail ----------------
__global__ void copy_logits_kernel(float* __restrict__ dst) {
    int i = blockIdx.x * blockDim.x + threadIdx.x;
    int n = TOK * NE;
    for (; i < n; i += gridDim.x * blockDim.x) dst[i] = g_logits[i];
}

// ---------------- host launcher ----------------
extern "C" void kernel_launch(void* const* d_in, const int* in_sizes, int n_in,
                              void* d_out, int out_size) {
    const float* x  = (const float*)d_in[0];
    const float* wg = (const float*)d_in[1];
    const float* w1 = (const float*)d_in[2];
    const float* w3 = (const float*)d_in[3];
    const float* w2 = (const float*)d_in[4];
    float* out = (float*)d_out;

    cudaFuncSetAttribute(gemm_a_mma, cudaFuncAttributeMaxDynamicSharedMemorySize, GA_TOTAL);
    cudaFuncSetAttribute(gemm_b_mma, cudaFuncAttributeMaxDynamicSharedMemorySize, GB_TOTAL);

    router_cvt_kernel<<<RB + CVB, 256>>>(x, wg, w1, w3, w2);   // 0: router + fp16 converts
    topk_kernel<<<(TOK + 255) / 256, 256>>>();                 // 1
    dispatch_kernel<<<NA / 256, 256>>>();                      // 2
    dim3 ga(FF / 64, CAP / 128, NE);                           // (8, 8, 64)
    gemm_a_mma<<<ga, 256, GA_TOTAL>>>();                       // 3 (profiled)
    zero_out_kernel<<<TOK * HD / 4 / 256, 256>>>((float4*)out);// 4
    dim3 gb(HD / 128, CAP / 128, NE);                          // (8, 8, 64)
    gemm_b_mma<<<gb, 256, GB_TOTAL>>>(out);                    // 5

    if ((size_t)out_size >= (size_t)TOK * HD + (size_t)TOK * NE) {
        copy_logits_kernel<<<256, 256>>>(out + (size_t)TOK * HD);
    }
}